// round 10
// baseline (speedup 1.0000x reference)
#include <cuda_runtime.h>
#include <math_constants.h>

#define B_     4
#define C_     256
#define H_     64
#define W_     64
#define NROI   128
#define OUTK   7
#define STRIDE 65              // smem row stride: bank = (y+x) & 31
#define PLANE  (H_ * STRIDE)   // floats per staged plane

// One block per (b, channel-pair, roi-parity). Stage BOTH channel planes in
// smem; pool the rois of batch b whose DETERMINISTIC compacted index has my
// parity (compaction order = original roi index, via ballot prefix sums, so
// both parity blocks see the identical partition).
// Bin bounds: exact integer math, bit-identical to the reference's f32 bounds
// (rel_err == 0 in rounds 4-8); precomputed per roi in phase 0.
__global__ __launch_bounds__(256) void roi_pool_plane2s(
    const float* __restrict__ feat,
    const int*   __restrict__ rois,
    float*       __restrict__ out)
{
    __shared__ float plane[2 * PLANE];
    __shared__ int   s_idx[NROI], s_x1[NROI], s_y1[NROI];
    __shared__ unsigned char s_hb[NROI][8], s_wb[NROI][8];
    __shared__ int   s_wcnt[4];            // matches per roi-warp (NROI=128 -> 4 warps)

    const int tid  = threadIdx.x;
    const int lane = tid & 31;
    const int wid  = tid >> 5;
    const int blk  = blockIdx.x;           // ((b*128 + cpair) << 1) | half
    const int half = blk & 1;
    const int bcp  = blk >> 1;
    const int b    = bcp >> 7;
    const int c0   = (bcp & 127) << 1;     // channels c0, c0+1

    // ---- phase 0a: match + deterministic positions via ballot ----
    bool match = false;
    if (tid < NROI)
        match = (__ldg(rois + tid * 5) == b);
    const unsigned mball = __ballot_sync(0xffffffffu, match);
    if (lane == 0 && wid < 4)
        s_wcnt[wid] = __popc(mball);
    __syncthreads();

    const int cnt = s_wcnt[0] + s_wcnt[1] + s_wcnt[2] + s_wcnt[3];

    // ---- phase 0b: compacted store at deterministic position ----
    if (match) {
        int p = __popc(mball & ((1u << lane) - 1u));
        for (int w = 0; w < wid; ++w) p += s_wcnt[w];

        const int x1 = __ldg(rois + tid * 5 + 1);
        const int y1 = __ldg(rois + tid * 5 + 2);
        const int x2 = __ldg(rois + tid * 5 + 3);
        const int y2 = __ldg(rois + tid * 5 + 4);
        const int rh = y2 - y1 + 1;        // 5..48
        const int rw = x2 - x1 + 1;        // 5..48
        s_idx[p] = tid;
        s_x1[p]  = x1;
        s_y1[p]  = y1;
        #pragma unroll
        for (int i = 0; i < 8; ++i) {
            s_hb[p][i] = (unsigned char)((i * rh) / 7);
            s_wb[p][i] = (unsigned char)((i * rw) / 7);
        }
    }

    // ---- phase 1: stage the two 64x64 planes (2048 float4, 8/thread) ----
    const float4* src = (const float4*)(feat + ((size_t)b * C_ + c0) * (H_ * W_));
    #pragma unroll
    for (int k = 0; k < 8; ++k) {
        const int g  = k * 256 + tid;       // float4 index over both planes
        const int pl = g >> 10;             // 1024 float4 per plane
        const int gi = g & 1023;
        const float4 v = __ldg(src + g);
        const int y = gi >> 4;              // 16 float4 per row
        const int x = (gi & 15) << 2;
        float* p = &plane[pl * PLANE + y * STRIDE + x];
        p[0] = v.x; p[1] = v.y; p[2] = v.z; p[3] = v.w;
    }
    __syncthreads();

    // ---- phase 2: my rois are compacted indices k = half, half+2, ... ----
    const int nmine = (cnt > half) ? ((cnt - half + 1) >> 1) : 0;
    const int total = nmine * (OUTK * OUTK);
    for (int u = tid; u < total; u += 256) {
        const int km  = u / 49;
        const int bin = u - km * 49;
        const int k   = half + (km << 1);
        const int i   = bin / OUTK;
        const int j   = bin - i * OUTK;

        const int hs = s_hb[k][i], he = s_hb[k][i + 1];
        const int ws = s_wb[k][j], we = s_wb[k][j + 1];
        const int nx = we - ws;
        const bool valid = (he > hs) && (nx > 0);

        const float* r0 = &plane[(s_y1[k] + hs) * STRIDE + s_x1[k] + ws];
        const float* r1 = r0 + PLANE;

        float a0 = -CUDART_INF_F, a1 = -CUDART_INF_F;   // channel c0
        float b0 = -CUDART_INF_F, b1 = -CUDART_INF_F;   // channel c0+1
        for (int y = hs; y < he; ++y) {
            int xx = 0;
            for (; xx + 2 <= nx; xx += 2) {
                a0 = fmaxf(a0, r0[xx]);     b0 = fmaxf(b0, r1[xx]);
                a1 = fmaxf(a1, r0[xx + 1]); b1 = fmaxf(b1, r1[xx + 1]);
            }
            if (xx < nx) { a0 = fmaxf(a0, r0[xx]); b0 = fmaxf(b0, r1[xx]); }
            r0 += STRIDE; r1 += STRIDE;
        }
        const float m0 = fmaxf(a0, a1);
        const float m1 = fmaxf(b0, b1);

        const size_t obase = ((size_t)s_idx[k] * C_ + c0) * (OUTK * OUTK) + bin;
        out[obase]      = valid ? m0 : 0.0f;
        out[obase + 49] = valid ? m1 : 0.0f;
    }
}

extern "C" void kernel_launch(void* const* d_in, const int* in_sizes, int n_in,
                              void* d_out, int out_size) {
    const float* features = (const float*)d_in[0];
    const int*   rois     = (const int*)d_in[1];
    float*       out      = (float*)d_out;

    // grid = B * (C/2) * 2 roi-halves = 1024 blocks
    roi_pool_plane2s<<<B_ * (C_ / 2) * 2, 256>>>(features, rois, out);
}